// round 5
// baseline (speedup 1.0000x reference)
#include <cuda_runtime.h>
#include <cuda_bf16.h>
#include <math.h>

#define IMG 224
#define HALF 112
#define OFF 56.0f
#define TL_BASE 38
#define TL_RANGE 18.0f
#define RPB 8            // output rows per block
#define THREADS 224      // one thread per output column (build phase)
#define HROWS 8          // staged-row capacity (worst case 6 needed)

// sigmoid(10*z) difference mask factor at coordinate v for center t, half-length l
__device__ __forceinline__ float mask1d(float v, float t, float l) {
    float z1 = 10.0f * (v - t + l);
    float z2 = 10.0f * (v - t - l);
    float s1 = 1.0f / (1.0f + __expf(-z1));
    float s2 = 1.0f / (1.0f + __expf(-z2));
    return s1 - s2;
}

__global__ __launch_bounds__(THREADS)
void attention_crop_kernel(const float* __restrict__ apn,
                           const float* __restrict__ in,
                           float* __restrict__ out) {
    const int b   = blockIdx.y;
    const int tid = threadIdx.x;

    // Per-batch crop params
    const float a0p = __ldg(&apn[b * 3 + 0]);
    const float a1p = __ldg(&apn[b * 3 + 1]);
    const float a2p = __ldg(&apn[b * 3 + 2]);
    const int tx = HALF + (int)truncf(a0p * OFF + 0.5f);
    const int ty = HALF + (int)truncf(a1p * OFF + 0.5f);
    const int tl = TL_BASE + (int)truncf((a2p + 1.0f) * 0.5f * TL_RANGE);
    const int in_size = 2 * tl;
    const float scale = (float)in_size * (1.0f / 224.0f);
    const float txf = (float)tx, tyf = (float)ty, tlf = (float)tl;

    // Column coefficients for col = tid (used in build phase), in registers
    float srcc = fmaxf((tid + 0.5f) * scale - 0.5f, 0.0f);
    int   ci0  = (int)srcc;
    float wc   = srcc - (float)ci0;
    int   ci1  = min(ci0 + 1, in_size - 1);
    const int   c0  = (ty - tl) + ci0;
    const int   c1  = (ty - tl) + ci1;
    const float a0c = (1.0f - wc) * mask1d((float)c0, tyf, tlf);
    const float a1c = wc          * mask1d((float)c1, tyf, tlf);

    // Row tables: crop-relative source row indices + fused vertical weights
    __shared__ int   s_i0[RPB];
    __shared__ int   s_i1[RPB];
    __shared__ float s_w0[RPB];   // (1-wr) * fx(r0)
    __shared__ float s_w1[RPB];   // wr     * fx(r1)
    __shared__ __align__(16) float h[HROWS * IMG];   // staged interp rows

    const int row_base = blockIdx.x * RPB;
    if (tid < RPB) {
        const int r = row_base + tid;
        float src = fmaxf((r + 0.5f) * scale - 0.5f, 0.0f);
        int   i0  = (int)src;
        float wr  = src - (float)i0;
        int   i1  = min(i0 + 1, in_size - 1);
        s_i0[tid] = i0;
        s_i1[tid] = i1;
        const float r0a = (float)((tx - tl) + i0);
        const float r1a = (float)((tx - tl) + i1);
        s_w0[tid] = (1.0f - wr) * mask1d(r0a, txf, tlf);
        s_w1[tid] = wr          * mask1d(r1a, txf, tlf);
    }
    __syncthreads();

    const int row_first = s_i0[0];                    // uniform
    const int nrows     = s_i1[RPB - 1] - row_first + 1;  // uniform, <= 6
    const int abs_first = (tx - tl) + row_first;

    const float* __restrict__ inb  = in  + (size_t)b * (3 * IMG * IMG);
    float*       __restrict__ outb = out + (size_t)b * (3 * IMG * IMG);

    // Consume-phase thread mapping: 4 consecutive cols per thread
    const int g  = tid % 56;        // column group -> cols 4g..4g+3
    const int ry = tid / 56;        // row offset within half-pass (0..3)

    #pragma unroll
    for (int ch = 0; ch < 3; ch++) {
        const float* __restrict__ p = inb + ch * (IMG * IMG);

        // Build: horizontally interpolated + mask-weighted rows into shared
        for (int q = 0; q < nrows; q++) {
            const float* rowp = p + (abs_first + q) * IMG;
            h[q * IMG + tid] = fmaf(a0c, __ldg(rowp + c0), a1c * __ldg(rowp + c1));
        }
        __syncthreads();

        // Consume: vertical combine, vectorized LDS.128 + STG.128
        #pragma unroll
        for (int pass = 0; pass < 2; pass++) {
            const int rr  = pass * 4 + ry;
            const int q0  = s_i0[rr] - row_first;
            const int q1  = s_i1[rr] - row_first;
            const float w0 = s_w0[rr];
            const float w1 = s_w1[rr];
            const float4 hv0 = *reinterpret_cast<const float4*>(&h[q0 * IMG + 4 * g]);
            const float4 hv1 = *reinterpret_cast<const float4*>(&h[q1 * IMG + 4 * g]);
            float4 o;
            o.x = fmaf(w0, hv0.x, w1 * hv1.x);
            o.y = fmaf(w0, hv0.y, w1 * hv1.y);
            o.z = fmaf(w0, hv0.z, w1 * hv1.z);
            o.w = fmaf(w0, hv0.w, w1 * hv1.w);
            *reinterpret_cast<float4*>(
                &outb[ch * (IMG * IMG) + (row_base + rr) * IMG + 4 * g]) = o;
        }
        if (ch < 2) __syncthreads();   // protect h before next channel's build
    }
}

extern "C" void kernel_launch(void* const* d_in, const int* in_sizes, int n_in,
                              void* d_out, int out_size) {
    const float* apn = (const float*)d_in[0];   // [256, 3]
    const float* in  = (const float*)d_in[1];   // [256, 3, 224, 224]
    float* out = (float*)d_out;                 // [256, 3, 224, 224]

    dim3 grid(IMG / RPB, 256);                  // (28 row-chunks, B)
    attention_crop_kernel<<<grid, THREADS>>>(apn, in, out);
}

// round 8
// speedup vs baseline: 1.2757x; 1.2757x over previous
#include <cuda_runtime.h>
#include <cuda_bf16.h>
#include <math.h>

#define IMG 224
#define HALF 112
#define OFF 56.0f
#define TL_BASE 38
#define TL_RANGE 18.0f
#define RPB 16           // output rows per block
#define THREADS 224
#define HCAP 10          // staged source-row capacity (max span for RPB=16, scale<0.492)

__device__ __forceinline__ float mask1d(float v, float t, float l) {
    float z1 = 10.0f * (v - t + l);
    float z2 = 10.0f * (v - t - l);
    float s1 = 1.0f / (1.0f + __expf(-z1));
    float s2 = 1.0f / (1.0f + __expf(-z2));
    return s1 - s2;
}

__global__ __launch_bounds__(THREADS)
void attention_crop_kernel(const float* __restrict__ apn,
                           const float* __restrict__ in,
                           float* __restrict__ out) {
    const int b   = blockIdx.y;
    const int tid = threadIdx.x;

    // Per-batch crop params
    const float a0p = __ldg(&apn[b * 3 + 0]);
    const float a1p = __ldg(&apn[b * 3 + 1]);
    const float a2p = __ldg(&apn[b * 3 + 2]);
    const int tx = HALF + (int)truncf(a0p * OFF + 0.5f);
    const int ty = HALF + (int)truncf(a1p * OFF + 0.5f);
    const int tl = TL_BASE + (int)truncf((a2p + 1.0f) * 0.5f * TL_RANGE);
    const int in_size = 2 * tl;
    const float scale = (float)in_size * (1.0f / 224.0f);
    const float txf = (float)tx, tyf = (float)ty, tlf = (float)tl;

    // Column coefficients for col = tid (registers)
    float srcc = fmaxf((tid + 0.5f) * scale - 0.5f, 0.0f);
    int   ci0  = (int)srcc;
    float wc   = srcc - (float)ci0;
    int   ci1  = min(ci0 + 1, in_size - 1);
    const int   c0  = (ty - tl) + ci0;
    const int   c1  = (ty - tl) + ci1;
    const float a0c = (1.0f - wc) * mask1d((float)c0, tyf, tlf);
    const float a1c = wc          * mask1d((float)c1, tyf, tlf);

    // Source-row window for this block (uniform, computed in registers by all threads)
    const int rb = blockIdx.x * RPB;
    const int i_first = (int)fmaxf((rb + 0.5f) * scale - 0.5f, 0.0f);
    const int abs_first = (tx - tl) + i_first;

    __shared__ int   s_q0[RPB];
    __shared__ int   s_q1[RPB];
    __shared__ float s_w0[RPB];
    __shared__ float s_w1[RPB];
    __shared__ __align__(16) float h[3 * HCAP * IMG];   // 26880 B

    if (tid < RPB) {
        const int r = rb + tid;
        float src = fmaxf((r + 0.5f) * scale - 0.5f, 0.0f);
        int   i0  = (int)src;
        float wr  = src - (float)i0;
        int   i1  = min(i0 + 1, in_size - 1);
        s_q0[tid] = i0 - i_first;
        s_q1[tid] = i1 - i_first;
        const float r0a = (float)((tx - tl) + i0);
        const float r1a = (float)((tx - tl) + i1);
        s_w0[tid] = (1.0f - wr) * mask1d(r0a, txf, tlf);
        s_w1[tid] = wr          * mask1d(r1a, txf, tlf);
    }

    // nrows (uniform): last needed source row index, relative
    {
        // computed below inline in build loop bound
    }
    const int i_last_lo = (int)fmaxf((rb + RPB - 1 + 0.5f) * scale - 0.5f, 0.0f);
    const int i_last    = min(i_last_lo + 1, in_size - 1);
    const int nrows     = i_last - i_first + 1;          // <= HCAP

    const float* __restrict__ inb  = in  + (size_t)b * (3 * IMG * IMG);
    float*       __restrict__ outb = out + (size_t)b * (3 * IMG * IMG);

    // ---- Build: all channels' horizontally-interpolated, mask-weighted rows ----
    {
        const float* p0 = inb + abs_first * IMG + c0;
        const float* p1 = inb + abs_first * IMG + c1;
        for (int q = 0; q < nrows; q++) {
            #pragma unroll
            for (int ch = 0; ch < 3; ch++) {
                const float v0 = __ldg(p0 + ch * (IMG * IMG) + q * IMG);
                const float v1 = __ldg(p1 + ch * (IMG * IMG) + q * IMG);
                h[(ch * HCAP + q) * IMG + tid] = fmaf(a0c, v0, a1c * v1);
            }
        }
    }
    __syncthreads();

    // ---- Consume: vertical combine, LDS.128 -> STG.128 ----
    const int g  = tid % 56;        // column group: cols 4g..4g+3
    const int ry = tid / 56;        // 0..3
    float* ob = outb + rb * IMG + 4 * g;

    #pragma unroll
    for (int ch = 0; ch < 3; ch++) {
        #pragma unroll
        for (int k = 0; k < 4; k++) {
            const int   rr = k * 4 + ry;     // warp-uniform row per warp group
            const int   q0 = s_q0[rr];
            const int   q1 = s_q1[rr];
            const float w0 = s_w0[rr];
            const float w1 = s_w1[rr];
            const float4 hv0 = *reinterpret_cast<const float4*>(&h[(ch * HCAP + q0) * IMG + 4 * g]);
            const float4 hv1 = *reinterpret_cast<const float4*>(&h[(ch * HCAP + q1) * IMG + 4 * g]);
            float4 o;
            o.x = fmaf(w0, hv0.x, w1 * hv1.x);
            o.y = fmaf(w0, hv0.y, w1 * hv1.y);
            o.z = fmaf(w0, hv0.z, w1 * hv1.z);
            o.w = fmaf(w0, hv0.w, w1 * hv1.w);
            *reinterpret_cast<float4*>(&ob[ch * (IMG * IMG) + rr * IMG]) = o;
        }
    }
}

extern "C" void kernel_launch(void* const* d_in, const int* in_sizes, int n_in,
                              void* d_out, int out_size) {
    const float* apn = (const float*)d_in[0];   // [256, 3]
    const float* in  = (const float*)d_in[1];   // [256, 3, 224, 224]
    float* out = (float*)d_out;                 // [256, 3, 224, 224]

    dim3 grid(IMG / RPB, 256);                  // (14 row-chunks, B)
    attention_crop_kernel<<<grid, THREADS>>>(apn, in, out);
}